// round 15
// baseline (speedup 1.0000x reference)
#include <cuda_runtime.h>
#include <cuda_fp16.h>
#include <cstdint>

// Problem shape (fixed by the dataset): N=10000, E=160000, IN=OUT=512, TC=256.
#define MAXN   10240
#define MAXE   163840
#define DIMK   512
#define DIMOUT 512
#define DIMTC  256

// Static device scratch (no runtime allocation allowed).
__device__ __half g_xw[MAXN * DIMOUT];  // x @ W  (fp16 gather traffic)
__device__ float  g_dinv[MAXN];         // rsqrt(deg)
__device__ float  g_tb[DIMOUT];         // b + bt + t_emb @ Wt
__device__ int    g_rowstart[MAXN + 1]; // CSR row offsets
__device__ int2   g_csr_sw[MAXE];       // {src, weight_bits} per CSR slot

// dynamic smem size for the mega kernel: builder needs the most
#define DYN_SMEM (MAXN * 8 + 4096)

// ---------------------------------------------------------------------------
// helpers
// ---------------------------------------------------------------------------
__device__ __forceinline__ float to_tf32(float x) {
    uint32_t u;
    asm("cvt.rna.tf32.f32 %0, %1;" : "=r"(u) : "f"(x));
    return __uint_as_float(u);
}

__device__ __forceinline__ void mma_tf32(float* d, const uint32_t* a, const uint32_t* b) {
    asm volatile(
        "mma.sync.aligned.m16n8k8.row.col.f32.tf32.tf32.f32 "
        "{%0,%1,%2,%3}, {%4,%5,%6,%7}, {%8,%9}, {%0,%1,%2,%3};"
        : "+f"(d[0]), "+f"(d[1]), "+f"(d[2]), "+f"(d[3])
        : "r"(a[0]), "r"(a[1]), "r"(a[2]), "r"(a[3]),
          "r"(b[0]), "r"(b[1]));
}

// ---------------------------------------------------------------------------
// MEGA KERNEL (one launch):
//   block 0          : full CSR build (count -> scan -> dinv -> fill) in SMEM
//   blocks 1..16     : tb[j] = b[j]+bt[j]+sum_k t_emb[k]*Wt[k,j]
//   blocks 17..      : TF32 tensor-core GEMM  xw = x @ W  (fp16 out)
// All roles independent; builder (~20us on 1 SM) hides under GEMM (~50us).
// ---------------------------------------------------------------------------
__global__ __launch_bounds__(256, 2)
void k_mega(const float* __restrict__ A,      // x
            const float* __restrict__ B,      // W
            __half* __restrict__ C,           // xw
            const float* __restrict__ t_emb,
            const float* __restrict__ Wt,
            const float* __restrict__ bias,
            const float* __restrict__ bt,
            float* __restrict__ tb,
            const int* __restrict__ ei,
            int* __restrict__ rowstart,
            float* __restrict__ dinv,
            int2* __restrict__ csr_sw,
            int N, int E) {
    extern __shared__ char dynsm[];
    int tid = threadIdx.x;

    if (blockIdx.x == 0) {
        // ----------------- CSR builder (256 threads, one block) -----------------
        int*   scount = (int*)dynsm;                    // [MAXN] count -> cursor
        float* sdinv  = (float*)(dynsm + MAXN * 4);     // [MAXN]
        int*   part   = (int*)(dynsm + MAXN * 8);       // [256] scan partials

        // Phase A: zero counts
        for (int i = tid; i < N; i += 256) scount[i] = 0;
        __syncthreads();

        // Phase B: histogram of dst (smem atomics, spread addresses)
        for (int e = tid; e < E; e += 256) {
            atomicAdd(&scount[ei[E + e]], 1);
        }
        __syncthreads();

        // Phase C: exclusive scan (chunk-per-thread + Hillis-Steele over 256)
        int PER = (N + 255) >> 8;
        int base = tid * PER;
        int s = 0;
        for (int q = 0; q < PER; q++) {
            int idx = base + q;
            if (idx < N) s += scount[idx];
        }
        part[tid] = s;
        __syncthreads();
        for (int off = 1; off < 256; off <<= 1) {
            int v = (tid >= off) ? part[tid - off] : 0;
            __syncthreads();
            part[tid] += v;
            __syncthreads();
        }
        int run = (tid > 0) ? part[tid - 1] : 0;
        for (int q = 0; q < PER; q++) {
            int idx = base + q;
            if (idx < N) {
                int c = scount[idx];
                rowstart[idx] = run;
                float dv = rsqrtf((float)c + 1.0f);
                sdinv[idx] = dv;
                dinv[idx]  = dv;
                scount[idx] = run;   // becomes cursor
                run += c;
            }
        }
        if (tid == 255) rowstart[N] = part[255];
        __syncthreads();

        // Phase D: fill CSR with precomputed edge weights
        for (int e = tid; e < E; e += 256) {
            int sN = ei[e];
            int d  = ei[E + e];
            float w = sdinv[sN] * sdinv[d];
            int pos = atomicAdd(&scount[d], 1);
            csr_sw[pos] = make_int2(sN, __float_as_int(w));
        }
        return;
    }

    if (blockIdx.x <= 16) {
        // ----------------- time-bias vector -----------------
        float* red = (float*)dynsm;   // [8][32]
        int jloc = tid & 31;
        int kc   = tid >> 5;
        int j    = ((int)blockIdx.x - 1) * 32 + jloc;
        float acc = 0.0f;
        int k0 = kc * 32;
#pragma unroll
        for (int k = 0; k < 32; k++) {
            acc += t_emb[k0 + k] * Wt[(k0 + k) * DIMOUT + j];
        }
        red[kc * 32 + jloc] = acc;
        __syncthreads();
        if (kc == 0) {
            float sum = bias[j] + bt[j];
#pragma unroll
            for (int q = 0; q < 8; q++) sum += red[q * 32 + jloc];
            tb[j] = sum;
        }
        return;
    }

    // ----------------- TF32 GEMM -----------------
    float* As = (float*)dynsm;          // [128*36]
    float* Bs = As + 128 * 36;          // [32*136]

    int gid  = (int)blockIdx.x - 17;
    int lane = tid & 31;
    int wid  = tid >> 5;
    int wm   = wid & 1;
    int wn   = wid >> 1;
    int g    = lane >> 2;
    int c    = lane & 3;

    int rowBase = (gid >> 2) * 128;
    int colBase = (gid & 3) * 128;

    float acc[4][4][4];
#pragma unroll
    for (int mt = 0; mt < 4; mt++)
#pragma unroll
        for (int nt = 0; nt < 4; nt++)
#pragma unroll
            for (int q = 0; q < 4; q++) acc[mt][nt][q] = 0.0f;

    int ar  = tid >> 3;
    int ac4 = tid & 7;
    int bkr = tid >> 5;
    int bc4 = tid & 31;

    for (int k0 = 0; k0 < DIMK; k0 += 32) {
#pragma unroll
        for (int j = 0; j < 4; j++) {
            int row  = ar + 32 * j;
            int grow = rowBase + row;
            float4 v = make_float4(0.f, 0.f, 0.f, 0.f);
            if (grow < N)
                v = *reinterpret_cast<const float4*>(&A[(size_t)grow * DIMK + k0 + ac4 * 4]);
            v.x = to_tf32(v.x); v.y = to_tf32(v.y);
            v.z = to_tf32(v.z); v.w = to_tf32(v.w);
            *reinterpret_cast<float4*>(&As[row * 36 + ac4 * 4]) = v;
        }
#pragma unroll
        for (int j = 0; j < 4; j++) {
            int k = bkr + 8 * j;
            float4 v = *reinterpret_cast<const float4*>(
                &B[(size_t)(k0 + k) * DIMOUT + colBase + bc4 * 4]);
            v.x = to_tf32(v.x); v.y = to_tf32(v.y);
            v.z = to_tf32(v.z); v.w = to_tf32(v.w);
            *reinterpret_cast<float4*>(&Bs[k * 136 + bc4 * 4]) = v;
        }
        __syncthreads();

#pragma unroll
        for (int kk = 0; kk < 32; kk += 8) {
            uint32_t afr[4][4];
            uint32_t bfr[4][2];
#pragma unroll
            for (int mt = 0; mt < 4; mt++) {
                int rb = wm * 64 + mt * 16;
                afr[mt][0] = __float_as_uint(As[(rb + g)     * 36 + kk + c]);
                afr[mt][1] = __float_as_uint(As[(rb + g + 8) * 36 + kk + c]);
                afr[mt][2] = __float_as_uint(As[(rb + g)     * 36 + kk + c + 4]);
                afr[mt][3] = __float_as_uint(As[(rb + g + 8) * 36 + kk + c + 4]);
            }
#pragma unroll
            for (int nt = 0; nt < 4; nt++) {
                int nb = wn * 32 + nt * 8;
                bfr[nt][0] = __float_as_uint(Bs[(kk + c)     * 136 + nb + g]);
                bfr[nt][1] = __float_as_uint(Bs[(kk + c + 4) * 136 + nb + g]);
            }
#pragma unroll
            for (int mt = 0; mt < 4; mt++)
#pragma unroll
                for (int nt = 0; nt < 4; nt++)
                    mma_tf32(acc[mt][nt], afr[mt], bfr[nt]);
        }
        __syncthreads();
    }

#pragma unroll
    for (int mt = 0; mt < 4; mt++) {
        int row = rowBase + wm * 64 + mt * 16 + g;
#pragma unroll
        for (int nt = 0; nt < 4; nt++) {
            int col = colBase + wn * 32 + nt * 8 + 2 * c;
            if (row < N)
                *reinterpret_cast<__half2*>(&C[(size_t)row * DIMOUT + col]) =
                    __floats2half2_rn(acc[mt][nt][0], acc[mt][nt][1]);
            if (row + 8 < N)
                *reinterpret_cast<__half2*>(&C[(size_t)(row + 8) * DIMOUT + col]) =
                    __floats2half2_rn(acc[mt][nt][2], acc[mt][nt][3]);
        }
    }
}

// ---------------------------------------------------------------------------
// K2: CSR gather (atomic-free). Edge list staged in SMEM to break the
// sw-load -> xw-load dependent chain; only the xw row load stays global.
// ---------------------------------------------------------------------------
__global__ __launch_bounds__(128) void k_gather(const int* __restrict__ rowstart,
                                                const int2* __restrict__ csr_sw,
                                                const __half* __restrict__ xw,
                                                const float* __restrict__ dinv,
                                                const float* __restrict__ tb,
                                                float* __restrict__ out, int N) {
    __shared__ int2 ssw[1024];
    int i = blockIdx.x;
    int t = threadIdx.x;
    int start = rowstart[i];
    int end   = rowstart[i + 1];
    float di  = dinv[i];

    float4 acc = *(reinterpret_cast<const float4*>(tb) + t);

    // self loop (weight dinv^2)
    {
        uint2 raw = __ldg(reinterpret_cast<const uint2*>(xw + (size_t)i * DIMOUT) + t);
        float2 f0 = __half22float2(*reinterpret_cast<__half2*>(&raw.x));
        float2 f1 = __half22float2(*reinterpret_cast<__half2*>(&raw.y));
        float w = di * di;
        acc.x += w * f0.x;
        acc.y += w * f0.y;
        acc.z += w * f1.x;
        acc.w += w * f1.y;
    }

    for (int chunk = start; chunk < end; chunk += 1024) {
        int cnt = min(end - chunk, 1024);
        for (int j = t; j < cnt; j += 128) ssw[j] = __ldg(&csr_sw[chunk + j]);
        __syncthreads();
        for (int j = 0; j < cnt; j++) {
            int2 sw = ssw[j];
            float w = __int_as_float(sw.y);
            uint2 raw = __ldg(reinterpret_cast<const uint2*>(xw + (size_t)sw.x * DIMOUT) + t);
            float2 f0 = __half22float2(*reinterpret_cast<__half2*>(&raw.x));
            float2 f1 = __half22float2(*reinterpret_cast<__half2*>(&raw.y));
            acc.x += w * f0.x;
            acc.y += w * f0.y;
            acc.z += w * f1.x;
            acc.w += w * f1.y;
        }
        __syncthreads();
    }
    *(reinterpret_cast<float4*>(out + (size_t)i * DIMOUT) + t) = acc;
}

// ---------------------------------------------------------------------------
// launch
// ---------------------------------------------------------------------------
extern "C" void kernel_launch(void* const* d_in, const int* in_sizes, int n_in,
                              void* d_out, int out_size) {
    const float* x    = (const float*)d_in[0];
    const float* temb = (const float*)d_in[1];
    const int*   ei   = (const int*)d_in[2];   // int32 (JAX x64 disabled)
    const float* W    = (const float*)d_in[3];
    const float* b    = (const float*)d_in[4];
    const float* Wt   = (const float*)d_in[5];
    const float* bt   = (const float*)d_in[6];
    float*       out  = (float*)d_out;

    int N = in_sizes[0] / DIMK;
    int E = in_sizes[2] / 2;

    __half* xw;   cudaGetSymbolAddress((void**)&xw,    g_xw);
    float* dinv;  cudaGetSymbolAddress((void**)&dinv,  g_dinv);
    float* tb;    cudaGetSymbolAddress((void**)&tb,    g_tb);
    int* rowst;   cudaGetSymbolAddress((void**)&rowst, g_rowstart);
    int2* csrsw;  cudaGetSymbolAddress((void**)&csrsw, g_csr_sw);

    static bool attrSet = false;
    if (!attrSet) {
        cudaFuncSetAttribute(k_mega, cudaFuncAttributeMaxDynamicSharedMemorySize,
                             DYN_SMEM);
        attrSet = true;
    }

    int gemmBlocks = 4 * ((N + 127) / 128);
    k_mega<<<17 + gemmBlocks, 256, DYN_SMEM>>>(x, W, xw, temb, Wt, b, bt, tb,
                                               ei, rowst, dinv, csrsw, N, E);

    k_gather<<<N, 128>>>(rowst, csrsw, xw, dinv, tb, out, N);
}

// round 16
// speedup vs baseline: 2.2227x; 2.2227x over previous
#include <cuda_runtime.h>
#include <cuda_fp16.h>
#include <cstdint>

// Problem shape (fixed by the dataset): N=10000, E=160000, IN=OUT=512, TC=256.
#define MAXN   10240
#define MAXE   163840
#define DIMK   512
#define DIMOUT 512
#define DIMTC  256

// Static device scratch (no runtime allocation allowed).
__device__ __half g_xw[MAXN * DIMOUT];  // x @ W  (fp16 gather traffic)
__device__ float  g_dinv[MAXN];         // rsqrt(deg)
__device__ float  g_tb[DIMOUT];         // b + bt + t_emb @ Wt
__device__ int    g_count[MAXN];        // in-degree (excl self loop)
__device__ int    g_rowstart[MAXN + 1]; // CSR row offsets
__device__ int    g_cursor[MAXN];       // fill cursors
__device__ int2   g_csr_sw[MAXE];       // {src, weight_bits} per CSR slot

// ---------------------------------------------------------------------------
// helpers
// ---------------------------------------------------------------------------
__device__ __forceinline__ uint32_t pack_h2(float lo, float hi) {
    __half2 h = __floats2half2_rn(lo, hi);
    return *reinterpret_cast<uint32_t*>(&h);
}

__device__ __forceinline__ void mma_f16(float* d, const uint32_t* a, const uint32_t* b) {
    asm volatile(
        "mma.sync.aligned.m16n8k16.row.col.f32.f16.f16.f32 "
        "{%0,%1,%2,%3}, {%4,%5,%6,%7}, {%8,%9}, {%0,%1,%2,%3};"
        : "+f"(d[0]), "+f"(d[1]), "+f"(d[2]), "+f"(d[3])
        : "r"(a[0]), "r"(a[1]), "r"(a[2]), "r"(a[3]),
          "r"(b[0]), "r"(b[1]));
}

// ---------------------------------------------------------------------------
// K1 (fused): blocks [0,16): tb[j] = b[j]+bt[j]+sum_k t_emb[k]*Wt[k,j]
//             blocks [16,...): count[i] = 0
// ---------------------------------------------------------------------------
__global__ void k_setup(const float* __restrict__ t_emb,
                        const float* __restrict__ Wt,
                        const float* __restrict__ b,
                        const float* __restrict__ bt,
                        float* __restrict__ tb,
                        int* __restrict__ count, int N) {
    if (blockIdx.x < 16) {
        __shared__ float red[8][32];
        int jloc = threadIdx.x & 31;
        int kc   = threadIdx.x >> 5;
        int j    = blockIdx.x * 32 + jloc;
        float acc = 0.0f;
        int k0 = kc * 32;
#pragma unroll
        for (int k = 0; k < 32; k++) {
            acc += t_emb[k0 + k] * Wt[(k0 + k) * DIMOUT + j];
        }
        red[kc][jloc] = acc;
        __syncthreads();
        if (kc == 0) {
            float s = b[j] + bt[j];
#pragma unroll
            for (int q = 0; q < 8; q++) s += red[q][jloc];
            tb[j] = s;
        }
    } else {
        int i = (blockIdx.x - 16) * blockDim.x + threadIdx.x;
        if (i < N) count[i] = 0;
    }
}

// ---------------------------------------------------------------------------
// K2 (fused): blocks [0,gemmBlocks): FP16 HMMA GEMM  C = A @ B  (fp16 out,
//             fp32 accumulate). blocks [gemmBlocks,...): dst histogram.
// A staged as half pairs along k (stride 20 uints, conflict-free frag LDS);
// B staged k-pair-packed: Bs[kp][n] = half2{B[2kp][n], B[2kp+1][n]},
// stride 136 uints (conflict-free).
// ---------------------------------------------------------------------------
__global__ __launch_bounds__(256, 2)
void k_gemm_count(const float* __restrict__ A,
                  const float* __restrict__ B,
                  __half* __restrict__ C, int N, int gemmBlocks,
                  const int* __restrict__ ei, int* __restrict__ count, int E) {
    if ((int)blockIdx.x >= gemmBlocks) {
        int base = ((int)blockIdx.x - gemmBlocks) * 1024 + threadIdx.x;
#pragma unroll
        for (int q = 0; q < 4; q++) {
            int e = base + q * 256;
            if (e < E) atomicAdd(&count[ei[E + e]], 1);
        }
        return;
    }

    __shared__ uint32_t As[128 * 20];   // 128 rows x 16 kp (stride 20) = 10 KB
    __shared__ uint32_t Bs[16 * 136];   // 16 kp rows x 128 n (stride 136) = 8.5 KB

    int tid  = threadIdx.x;
    int lane = tid & 31;
    int wid  = tid >> 5;
    int wm   = wid & 1;
    int wn   = wid >> 1;
    int g    = lane >> 2;
    int c    = lane & 3;

    int rowBase = ((int)blockIdx.x >> 2) * 128;
    int colBase = ((int)blockIdx.x & 3) * 128;

    float acc[4][4][4];
#pragma unroll
    for (int mt = 0; mt < 4; mt++)
#pragma unroll
        for (int nt = 0; nt < 4; nt++)
#pragma unroll
            for (int q = 0; q < 4; q++) acc[mt][nt][q] = 0.0f;

    int ar  = tid >> 3;        // 0..31 A row group
    int ac4 = tid & 7;         // float4 (=2 uints) slot within 32-k row
    int bkp = tid >> 5;        // 0..7 kp row group for B
    int bn4 = tid & 31;        // 4-col group for B

    for (int k0 = 0; k0 < DIMK; k0 += 32) {
        // A tile: 128 rows x 32 k (halves), converted from fp32
#pragma unroll
        for (int j = 0; j < 4; j++) {
            int row  = ar + 32 * j;
            int grow = rowBase + row;
            float4 v = make_float4(0.f, 0.f, 0.f, 0.f);
            if (grow < N)
                v = *reinterpret_cast<const float4*>(&A[(size_t)grow * DIMK + k0 + ac4 * 4]);
            uint2 u;
            u.x = pack_h2(v.x, v.y);
            u.y = pack_h2(v.z, v.w);
            *reinterpret_cast<uint2*>(&As[row * 20 + ac4 * 2]) = u;
        }
        // B tile: 16 kp rows x 128 n, interleave two k rows into half2 pairs
#pragma unroll
        for (int j = 0; j < 2; j++) {
            int kp = bkp + 8 * j;
            int k  = k0 + 2 * kp;
            const float4 va = *reinterpret_cast<const float4*>(
                &B[(size_t)k * DIMOUT + colBase + bn4 * 4]);
            const float4 vb = *reinterpret_cast<const float4*>(
                &B[(size_t)(k + 1) * DIMOUT + colBase + bn4 * 4]);
            uint4 u;
            u.x = pack_h2(va.x, vb.x);
            u.y = pack_h2(va.y, vb.y);
            u.z = pack_h2(va.z, vb.z);
            u.w = pack_h2(va.w, vb.w);
            *reinterpret_cast<uint4*>(&Bs[kp * 136 + bn4 * 4]) = u;
        }
        __syncthreads();

#pragma unroll
        for (int s = 0; s < 2; s++) {       // two k16 steps per 32-k tile
            int kb = 8 * s;                  // kp base
            uint32_t afr[4][4];
            uint32_t bfr[4][2];
#pragma unroll
            for (int mt = 0; mt < 4; mt++) {
                int rb = wm * 64 + mt * 16;
                afr[mt][0] = As[(rb + g)     * 20 + kb + c];
                afr[mt][1] = As[(rb + g + 8) * 20 + kb + c];
                afr[mt][2] = As[(rb + g)     * 20 + kb + c + 4];
                afr[mt][3] = As[(rb + g + 8) * 20 + kb + c + 4];
            }
#pragma unroll
            for (int nt = 0; nt < 4; nt++) {
                int nb = wn * 32 + nt * 8;
                bfr[nt][0] = Bs[(kb + c)     * 136 + nb + g];
                bfr[nt][1] = Bs[(kb + c + 4) * 136 + nb + g];
            }
#pragma unroll
            for (int mt = 0; mt < 4; mt++)
#pragma unroll
                for (int nt = 0; nt < 4; nt++)
                    mma_f16(acc[mt][nt], afr[mt], bfr[nt]);
        }
        __syncthreads();
    }

    // epilogue: fp16 out, __half2 stores (c0,c1)=(row,2c), (c2,c3)=(row+8,2c)
#pragma unroll
    for (int mt = 0; mt < 4; mt++) {
        int row = rowBase + wm * 64 + mt * 16 + g;
#pragma unroll
        for (int nt = 0; nt < 4; nt++) {
            int col = colBase + wn * 32 + nt * 8 + 2 * c;
            if (row < N)
                *reinterpret_cast<__half2*>(&C[(size_t)row * DIMOUT + col]) =
                    __floats2half2_rn(acc[mt][nt][0], acc[mt][nt][1]);
            if (row + 8 < N)
                *reinterpret_cast<__half2*>(&C[(size_t)(row + 8) * DIMOUT + col]) =
                    __floats2half2_rn(acc[mt][nt][2], acc[mt][nt][3]);
        }
    }
}

// ---------------------------------------------------------------------------
// K3: exclusive scan of count -> rowstart[0..N] + cursor copy + dinv
// ---------------------------------------------------------------------------
__global__ __launch_bounds__(1024) void k_scan(const int* __restrict__ count,
                                               int* __restrict__ rowstart,
                                               int* __restrict__ cursor,
                                               float* __restrict__ dinv, int N) {
    __shared__ int part[1024];
    int tid = threadIdx.x;
    int PER = (N + 1023) >> 10;
    int base = tid * PER;
    int s = 0;
    for (int q = 0; q < PER; q++) {
        int idx = base + q;
        s += (idx < N) ? count[idx] : 0;
    }
    part[tid] = s;
    __syncthreads();
    for (int off = 1; off < 1024; off <<= 1) {
        int v = (tid >= off) ? part[tid - off] : 0;
        __syncthreads();
        part[tid] += v;
        __syncthreads();
    }
    int run = (tid > 0) ? part[tid - 1] : 0;
    for (int q = 0; q < PER; q++) {
        int idx = base + q;
        if (idx <= N) {
            rowstart[idx] = run;
            if (idx < N) cursor[idx] = run;
        }
        if (idx < N) {
            int c = count[idx];
            dinv[idx] = rsqrtf((float)c + 1.0f);
            run += c;
        }
    }
}

// ---------------------------------------------------------------------------
// K4: CSR fill: csr_sw[pos] = {src, dinv[src]*dinv[dst]}, pos = cursor[dst]++
// ---------------------------------------------------------------------------
__global__ void k_fill(const int* __restrict__ ei, int* cursor,
                       const float* __restrict__ dinv,
                       int2* __restrict__ csr_sw, int E) {
    int e = blockIdx.x * blockDim.x + threadIdx.x;
    if (e < E) {
        int s = ei[e];
        int d = ei[E + e];
        float w = dinv[s] * dinv[d];
        int pos = atomicAdd(&cursor[d], 1);
        csr_sw[pos] = make_int2(s, __float_as_int(w));
    }
}

// ---------------------------------------------------------------------------
// K5: CSR gather (atomic-free), fp16 xw, precomputed edge weights.
// Edge list staged through SMEM (measured 18.6us in R15).
// ---------------------------------------------------------------------------
__global__ __launch_bounds__(128) void k_gather(const int* __restrict__ rowstart,
                                                const int2* __restrict__ csr_sw,
                                                const __half* __restrict__ xw,
                                                const float* __restrict__ dinv,
                                                const float* __restrict__ tb,
                                                float* __restrict__ out, int N) {
    __shared__ int2 ssw[1024];
    int i = blockIdx.x;
    int t = threadIdx.x;
    int start = rowstart[i];
    int end   = rowstart[i + 1];
    float di  = dinv[i];

    float4 acc = *(reinterpret_cast<const float4*>(tb) + t);

    // self loop (weight dinv^2)
    {
        uint2 raw = __ldg(reinterpret_cast<const uint2*>(xw + (size_t)i * DIMOUT) + t);
        float2 f0 = __half22float2(*reinterpret_cast<__half2*>(&raw.x));
        float2 f1 = __half22float2(*reinterpret_cast<__half2*>(&raw.y));
        float w = di * di;
        acc.x += w * f0.x;
        acc.y += w * f0.y;
        acc.z += w * f1.x;
        acc.w += w * f1.y;
    }

    for (int chunk = start; chunk < end; chunk += 1024) {
        int cnt = min(end - chunk, 1024);
        for (int j = t; j < cnt; j += 128) ssw[j] = __ldg(&csr_sw[chunk + j]);
        __syncthreads();
        for (int j = 0; j < cnt; j++) {
            int2 sw = ssw[j];
            float w = __int_as_float(sw.y);
            uint2 raw = __ldg(reinterpret_cast<const uint2*>(xw + (size_t)sw.x * DIMOUT) + t);
            float2 f0 = __half22float2(*reinterpret_cast<__half2*>(&raw.x));
            float2 f1 = __half22float2(*reinterpret_cast<__half2*>(&raw.y));
            acc.x += w * f0.x;
            acc.y += w * f0.y;
            acc.z += w * f1.x;
            acc.w += w * f1.y;
        }
        __syncthreads();
    }
    *(reinterpret_cast<float4*>(out + (size_t)i * DIMOUT) + t) = acc;
}

// ---------------------------------------------------------------------------
// launch
// ---------------------------------------------------------------------------
extern "C" void kernel_launch(void* const* d_in, const int* in_sizes, int n_in,
                              void* d_out, int out_size) {
    const float* x    = (const float*)d_in[0];
    const float* temb = (const float*)d_in[1];
    const int*   ei   = (const int*)d_in[2];   // int32 (JAX x64 disabled)
    const float* W    = (const float*)d_in[3];
    const float* b    = (const float*)d_in[4];
    const float* Wt   = (const float*)d_in[5];
    const float* bt   = (const float*)d_in[6];
    float*       out  = (float*)d_out;

    int N = in_sizes[0] / DIMK;
    int E = in_sizes[2] / 2;

    __half* xw;   cudaGetSymbolAddress((void**)&xw,    g_xw);
    float* dinv;  cudaGetSymbolAddress((void**)&dinv,  g_dinv);
    float* tb;    cudaGetSymbolAddress((void**)&tb,    g_tb);
    int* count;   cudaGetSymbolAddress((void**)&count, g_count);
    int* rowst;   cudaGetSymbolAddress((void**)&rowst, g_rowstart);
    int* cursor;  cudaGetSymbolAddress((void**)&cursor,g_cursor);
    int2* csrsw;  cudaGetSymbolAddress((void**)&csrsw, g_csr_sw);

    int zeroBlocks = (N + 255) / 256;
    k_setup<<<16 + zeroBlocks, 256>>>(temb, Wt, b, bt, tb, count, N);

    int gemmBlocks  = 4 * ((N + 127) / 128);
    int countBlocks = (E + 1023) / 1024;
    k_gemm_count<<<gemmBlocks + countBlocks, 256>>>(x, W, xw, N, gemmBlocks,
                                                    ei, count, E);

    k_scan<<<1, 1024>>>(count, rowst, cursor, dinv, N);
    k_fill<<<(E + 255) / 256, 256>>>(ei, cursor, dinv, csrsw, E);

    k_gather<<<N, 128>>>(rowst, csrsw, xw, dinv, tb, out, N);
}